// round 2
// baseline (speedup 1.0000x reference)
#include <cuda_runtime.h>
#include <cuda_bf16.h>

#define NN 100000
#define NE 3200000
#define NB_SCAN 196   // ceil(NN/512)

// ---- scratch (device globals; no allocation allowed) ----
__device__ int   g_src[NE];
__device__ int   g_dst[NE];
__device__ int   g_csr_src[NE];
__device__ float g_csr_coef[NE];
__device__ float g_degw[NN];
__device__ float g_dinv[NN];
__device__ int   g_cnt[NN];
__device__ int   g_rowptr[NN + 1];
__device__ int   g_cursor[NN];
__device__ int   g_bsum[256];
__device__ float g_xw1[NN * 16];
__device__ float g_h[NN * 16];
__device__ float g_z[NN * 32];

// ---- 1) zero degree/count ----
__global__ void k_zero() {
    int i = blockIdx.x * blockDim.x + threadIdx.x;
    if (i < NN) { g_degw[i] = 0.f; g_cnt[i] = 0; }
}

// ---- 2) one pass over int32 edge list: weighted degree + count ----
__global__ void k_edges_pre(const int* __restrict__ ei,
                            const float* __restrict__ ew, int E) {
    int i = blockIdx.x * blockDim.x + threadIdx.x;
    if (i >= E) return;
    int s = ei[i];
    int d = ei[E + i];
    g_src[i] = s;
    g_dst[i] = d;
    atomicAdd(&g_degw[d], ew[i]);
    atomicAdd(&g_cnt[d], 1);
}

// ---- 3) block-level exclusive scan of counts ----
__global__ void k_scan1() {
    __shared__ int sh[512];
    int tid = threadIdx.x;
    int i = blockIdx.x * 512 + tid;
    int v = (i < NN) ? g_cnt[i] : 0;
    sh[tid] = v; __syncthreads();
    for (int off = 1; off < 512; off <<= 1) {
        int t = (tid >= off) ? sh[tid - off] : 0;
        __syncthreads();
        sh[tid] += t;
        __syncthreads();
    }
    if (i < NN) g_rowptr[i] = sh[tid] - v;   // exclusive within block
    if (tid == 511) g_bsum[blockIdx.x] = sh[511];
}

__global__ void k_scan2() {
    __shared__ int sh[256];
    int tid = threadIdx.x;
    int v = (tid < NB_SCAN) ? g_bsum[tid] : 0;
    sh[tid] = v; __syncthreads();
    for (int off = 1; off < 256; off <<= 1) {
        int t = (tid >= off) ? sh[tid - off] : 0;
        __syncthreads();
        sh[tid] += t;
        __syncthreads();
    }
    if (tid < NB_SCAN) g_bsum[tid] = sh[tid] - v;  // exclusive
}

__global__ void k_scan3(int E) {
    int i = blockIdx.x * blockDim.x + threadIdx.x;
    if (i < NN) {
        int r = g_rowptr[i] + g_bsum[i >> 9];
        g_rowptr[i] = r;
        g_cursor[i] = r;
    }
    if (i == 0) g_rowptr[NN] = E;
}

// ---- 4) dinv = rsqrt(deg + 1)   (self-loop weight 1; always > 0) ----
__global__ void k_dinv() {
    int i = blockIdx.x * blockDim.x + threadIdx.x;
    if (i < NN) g_dinv[i] = rsqrtf(g_degw[i] + 1.0f);
}

// ---- 5) scatter edges into CSR; coef = dinv[s]*ew*dinv[d] (reused by BOTH layers) ----
__global__ void k_scatter(const float* __restrict__ ew, int E) {
    int i = blockIdx.x * blockDim.x + threadIdx.x;
    if (i >= E) return;
    int d = g_dst[i];
    int s = g_src[i];
    int pos = atomicAdd(&g_cursor[d], 1);
    g_csr_src[pos] = s;
    g_csr_coef[pos] = g_dinv[s] * ew[i] * g_dinv[d];
}

// ---- 6) xw1 = x @ W1   (128 -> 16), 8 nodes per 128-thread block ----
__global__ void k_xw(const float* __restrict__ x, const float* __restrict__ W1) {
    __shared__ float Ws[128 * 16];
    __shared__ float xs[8 * 128];
    int tid = threadIdx.x;
    int base = blockIdx.x * 8;
    for (int i = tid; i < 2048; i += 128) Ws[i] = W1[i];
    for (int i = tid; i < 1024; i += 128) xs[i] = x[(long long)base * 128 + i];
    __syncthreads();
    int r = tid >> 4, c = tid & 15;
    float acc = 0.f;
#pragma unroll
    for (int k = 0; k < 128; k++) acc = fmaf(xs[r * 128 + k], Ws[k * 16 + c], acc);
    g_xw1[(base + r) * 16 + c] = acc;
}

// ---- 7) layer-1 aggregation + bias + relu; 16 threads per node ----
__global__ void k_agg1(const float* __restrict__ b1) {
    int t = blockIdx.x * blockDim.x + threadIdx.x;
    int node = t >> 4;
    int c = t & 15;
    if (node >= NN) return;
    int j0 = g_rowptr[node], j1 = g_rowptr[node + 1];
    float dv = g_dinv[node];
    float acc = g_xw1[node * 16 + c] * dv * dv;   // self-loop term
#pragma unroll 4
    for (int j = j0; j < j1; j++) {
        int s = g_csr_src[j];
        float w = g_csr_coef[j];
        acc = fmaf(g_xw1[s * 16 + c], w, acc);
    }
    g_h[node * 16 + c] = fmaxf(acc + b1[c], 0.f);
}

// ---- 8) z = h @ W2   (16 -> 32), 8 nodes per 256-thread block ----
__global__ void k_z(const float* __restrict__ W2) {
    __shared__ float Ws[16 * 32];
    __shared__ float hs[8 * 16];
    int tid = threadIdx.x;
    int base = blockIdx.x * 8;
    for (int i = tid; i < 512; i += 256) Ws[i] = W2[i];
    if (tid < 128) hs[tid] = g_h[base * 16 + tid];
    __syncthreads();
    int r = tid >> 5, c = tid & 31;
    float acc = 0.f;
#pragma unroll
    for (int k = 0; k < 16; k++) acc = fmaf(hs[r * 16 + k], Ws[k * 32 + c], acc);
    g_z[(base + r) * 32 + c] = acc;
}

// ---- 9) layer-2 aggregation + bias; 1 warp per node ----
__global__ void k_agg2(const float* __restrict__ b2, float* __restrict__ out) {
    int t = blockIdx.x * blockDim.x + threadIdx.x;
    int node = t >> 5;
    int c = t & 31;
    if (node >= NN) return;
    int j0 = g_rowptr[node], j1 = g_rowptr[node + 1];
    float dv = g_dinv[node];
    float acc = g_z[node * 32 + c] * dv * dv;     // self-loop term
#pragma unroll 4
    for (int j = j0; j < j1; j++) {
        int s = g_csr_src[j];
        float w = g_csr_coef[j];
        acc = fmaf(g_z[s * 32 + c], w, acc);
    }
    out[node * 32 + c] = acc + b2[c];
}

extern "C" void kernel_launch(void* const* d_in, const int* in_sizes, int n_in,
                              void* d_out, int out_size) {
    const float* x  = (const float*)d_in[0];
    const int*   ei = (const int*)d_in[1];     // JAX default: int64 demoted to int32
    const float* ew = (const float*)d_in[2];
    const float* W1 = (const float*)d_in[3];
    const float* b1 = (const float*)d_in[4];
    const float* W2 = (const float*)d_in[5];
    const float* b2 = (const float*)d_in[6];
    float* out = (float*)d_out;
    int E = in_sizes[2];           // 3200000

    int nblkN = (NN + 255) / 256;
    int nblkE = (E + 255) / 256;

    k_zero<<<nblkN, 256>>>();
    k_edges_pre<<<nblkE, 256>>>(ei, ew, E);
    k_scan1<<<NB_SCAN, 512>>>();
    k_scan2<<<1, 256>>>();
    k_scan3<<<nblkN, 256>>>(E);
    k_dinv<<<nblkN, 256>>>();
    k_scatter<<<nblkE, 256>>>(ew, E);
    k_xw<<<NN / 8, 128>>>(x, W1);
    k_agg1<<<NN / 16, 256>>>(b1);
    k_z<<<NN / 8, 256>>>(W2);
    k_agg2<<<NN / 8, 256>>>(b2, out);
}

// round 5
// speedup vs baseline: 1.1655x; 1.1655x over previous
#include <cuda_runtime.h>
#include <cuda_bf16.h>

#define NN 100000
#define NE 3200000
#define NB_SCAN 196   // ceil(NN/512)

// ---- scratch (device globals; no allocation allowed) ----
__device__ int2  g_csr[NE];        // {src, coef as bits}
__device__ float g_degw[NN];
__device__ float g_dinv[NN];
__device__ int   g_cnt[NN];
__device__ int   g_rowptr[NN + 1];
__device__ int   g_cursor[NN];
__device__ int   g_bsum[256];
__device__ float g_xw1[NN * 16];   // also reused as g_az (layer-2 aggregate) after k_agg1
__device__ float g_h[NN * 16];

// ---- 1) zero degree/count ----
__global__ void k_zero() {
    int i = blockIdx.x * blockDim.x + threadIdx.x;
    if (i < NN) { g_degw[i] = 0.f; g_cnt[i] = 0; }
}

// ---- 2) dst-half pass: weighted degree + count ----
__global__ void k_pre(const int* __restrict__ ei, const float* __restrict__ ew, int E) {
    int i = blockIdx.x * blockDim.x + threadIdx.x;
    if (i >= E) return;
    int d = ei[E + i];
    atomicAdd(&g_degw[d], ew[i]);
    atomicAdd(&g_cnt[d], 1);
}

// ---- 3) block-level exclusive scan of counts ----
__global__ void k_scan1() {
    __shared__ int sh[512];
    int tid = threadIdx.x;
    int i = blockIdx.x * 512 + tid;
    int v = (i < NN) ? g_cnt[i] : 0;
    sh[tid] = v; __syncthreads();
    for (int off = 1; off < 512; off <<= 1) {
        int t = (tid >= off) ? sh[tid - off] : 0;
        __syncthreads();
        sh[tid] += t;
        __syncthreads();
    }
    if (i < NN) g_rowptr[i] = sh[tid] - v;
    if (tid == 511) g_bsum[blockIdx.x] = sh[511];
}

__global__ void k_scan2() {
    __shared__ int sh[256];
    int tid = threadIdx.x;
    int v = (tid < NB_SCAN) ? g_bsum[tid] : 0;
    sh[tid] = v; __syncthreads();
    for (int off = 1; off < 256; off <<= 1) {
        int t = (tid >= off) ? sh[tid - off] : 0;
        __syncthreads();
        sh[tid] += t;
        __syncthreads();
    }
    if (tid < NB_SCAN) g_bsum[tid] = sh[tid] - v;
}

__global__ void k_scan3(int E) {
    int i = blockIdx.x * blockDim.x + threadIdx.x;
    if (i < NN) {
        int r = g_rowptr[i] + g_bsum[i >> 9];
        g_rowptr[i] = r;
        g_cursor[i] = r;
    }
    if (i == 0) g_rowptr[NN] = E;
}

// ---- 4) dinv = rsqrt(deg + 1) ----
__global__ void k_dinv() {
    int i = blockIdx.x * blockDim.x + threadIdx.x;
    if (i < NN) g_dinv[i] = rsqrtf(g_degw[i] + 1.0f);
}

// ---- 5) scatter: one int2 {src, coef} per edge ----
__global__ void k_scatter(const int* __restrict__ ei, const float* __restrict__ ew, int E) {
    int i = blockIdx.x * blockDim.x + threadIdx.x;
    if (i >= E) return;
    int s = ei[i];
    int d = ei[E + i];
    float coef = __ldg(&g_dinv[s]) * ew[i] * __ldg(&g_dinv[d]);
    int pos = atomicAdd(&g_cursor[d], 1);
    g_csr[pos] = make_int2(s, __float_as_int(coef));
}

// ---- 6) xw1 = x @ W1 (128 -> 16), 8 nodes per 128-thread block ----
__global__ void k_xw(const float* __restrict__ x, const float* __restrict__ W1) {
    __shared__ float Ws[128 * 16];
    __shared__ float xs[8 * 128];
    int tid = threadIdx.x;
    int base = blockIdx.x * 8;
    for (int i = tid; i < 2048; i += 128) Ws[i] = W1[i];
    for (int i = tid; i < 1024; i += 128) xs[i] = x[(long long)base * 128 + i];
    __syncthreads();
    int r = tid >> 4, c = tid & 15;
    float acc = 0.f;
#pragma unroll
    for (int k = 0; k < 128; k++) acc = fmaf(xs[r * 128 + k], Ws[k * 16 + c], acc);
    g_xw1[(base + r) * 16 + c] = acc;
}

// ---- 7) layer-1 aggregation + bias + relu; 16 threads per node ----
__global__ void k_agg1(const float* __restrict__ b1) {
    int t = blockIdx.x * blockDim.x + threadIdx.x;
    int node = t >> 4;
    int c = t & 15;
    if (node >= NN) return;
    int j0 = g_rowptr[node], j1 = g_rowptr[node + 1];
    float dv = g_dinv[node];
    float acc = g_xw1[node * 16 + c] * dv * dv;   // self-loop
#pragma unroll 4
    for (int j = j0; j < j1; j++) {
        int2 e = g_csr[j];
        acc = fmaf(g_xw1[e.x * 16 + c], __int_as_float(e.y), acc);
    }
    g_h[node * 16 + c] = fmaxf(acc + b1[c], 0.f);
}

// ---- 8) layer-2 aggregation over h (16ch); result into g_xw1 (xw1 is dead now) ----
__global__ void k_agg2() {
    int t = blockIdx.x * blockDim.x + threadIdx.x;
    int node = t >> 4;
    int c = t & 15;
    if (node >= NN) return;
    int j0 = g_rowptr[node], j1 = g_rowptr[node + 1];
    float dv = g_dinv[node];
    float acc = g_h[node * 16 + c] * dv * dv;     // self-loop
#pragma unroll 4
    for (int j = j0; j < j1; j++) {
        int2 e = g_csr[j];
        acc = fmaf(g_h[e.x * 16 + c], __int_as_float(e.y), acc);
    }
    g_xw1[node * 16 + c] = acc;                   // az stored in reused buffer
}

// ---- 9) out = az @ W2 + b2 (16 -> 32), 8 nodes per 256-thread block ----
__global__ void k_out(const float* __restrict__ W2, const float* __restrict__ b2,
                      float* __restrict__ out) {
    __shared__ float Ws[16 * 32];
    __shared__ float hs[8 * 16];
    int tid = threadIdx.x;
    int base = blockIdx.x * 8;
    for (int i = tid; i < 512; i += 256) Ws[i] = W2[i];
    if (tid < 128) hs[tid] = g_xw1[base * 16 + tid];   // az
    __syncthreads();
    int r = tid >> 5, c = tid & 31;
    float acc = b2[c];
#pragma unroll
    for (int k = 0; k < 16; k++) acc = fmaf(hs[r * 16 + k], Ws[k * 32 + c], acc);
    out[(base + r) * 32 + c] = acc;
}

extern "C" void kernel_launch(void* const* d_in, const int* in_sizes, int n_in,
                              void* d_out, int out_size) {
    const float* x  = (const float*)d_in[0];
    const int*   ei = (const int*)d_in[1];
    const float* ew = (const float*)d_in[2];
    const float* W1 = (const float*)d_in[3];
    const float* b1 = (const float*)d_in[4];
    const float* W2 = (const float*)d_in[5];
    const float* b2 = (const float*)d_in[6];
    float* out = (float*)d_out;
    int E = in_sizes[2];           // 3200000

    int nblkN = (NN + 255) / 256;
    int nblkE = (E + 255) / 256;
    int nblkA = (NN * 16 + 255) / 256;

    k_zero<<<nblkN, 256>>>();
    k_pre<<<nblkE, 256>>>(ei, ew, E);
    k_scan1<<<NB_SCAN, 512>>>();
    k_scan2<<<1, 256>>>();
    k_scan3<<<nblkN, 256>>>(E);
    k_dinv<<<nblkN, 256>>>();
    k_scatter<<<nblkE, 256>>>(ei, ew, E);
    k_xw<<<NN / 8, 128>>>(x, W1);
    k_agg1<<<nblkA, 256>>>(b1);
    k_agg2<<<nblkA, 256>>>();
    k_out<<<NN / 8, 256>>>(W2, b2, out);
}

// round 6
// speedup vs baseline: 1.4097x; 1.2095x over previous
#include <cuda_runtime.h>
#include <cuda_bf16.h>

#define NN 100000
#define NE 3200000
#define NB_SCAN 196   // ceil(NN/512)

// ---- scratch (device globals; no allocation allowed) ----
__device__ int2  g_csr[NE];                 // {src, coef as bits}
__device__ unsigned long long g_cd[NN];     // count<<40 | fixed-point weighted degree
__device__ float g_dinv[NN];
__device__ int   g_rowptr[NN + 1];
__device__ int   g_cursor[NN];
__device__ int   g_bsum[256];
__device__ float g_xw1[NN * 16];            // reused as az after k_agg1
__device__ float g_h[NN * 16];

// ---- 1) zero packed count/degree ----
__global__ void k_zero() {
    int i = blockIdx.x * blockDim.x + threadIdx.x;
    if (i < NN) g_cd[i] = 0ull;
}

// ---- 2) dst-half pass: ONE u64 atomic per edge (count + fixed-point degw) ----
__global__ void k_pre(const int* __restrict__ ei, const float* __restrict__ ew, int E) {
    int i = blockIdx.x * blockDim.x + threadIdx.x;
    if (i >= E) return;
    int d = ei[E + i];
    unsigned int fx = __float2uint_rn(ew[i] * 1048576.0f);   // 2^20 fixed point, < 2^20
    unsigned long long pk = (1ull << 40) | (unsigned long long)fx;
    atomicAdd(&g_cd[d], pk);
}

// ---- 3) block-level exclusive scan of counts ----
__global__ void k_scan1() {
    __shared__ int sh[512];
    int tid = threadIdx.x;
    int i = blockIdx.x * 512 + tid;
    int v = (i < NN) ? (int)(g_cd[i] >> 40) : 0;
    sh[tid] = v; __syncthreads();
    for (int off = 1; off < 512; off <<= 1) {
        int t = (tid >= off) ? sh[tid - off] : 0;
        __syncthreads();
        sh[tid] += t;
        __syncthreads();
    }
    if (i < NN) g_rowptr[i] = sh[tid] - v;
    if (tid == 511) g_bsum[blockIdx.x] = sh[511];
}

__global__ void k_scan2() {
    __shared__ int sh[256];
    int tid = threadIdx.x;
    int v = (tid < NB_SCAN) ? g_bsum[tid] : 0;
    sh[tid] = v; __syncthreads();
    for (int off = 1; off < 256; off <<= 1) {
        int t = (tid >= off) ? sh[tid - off] : 0;
        __syncthreads();
        sh[tid] += t;
        __syncthreads();
    }
    if (tid < NB_SCAN) g_bsum[tid] = sh[tid] - v;
}

// ---- 4) finalize rowptr + cursor + dinv (fused) ----
__global__ void k_scan3(int E) {
    int i = blockIdx.x * blockDim.x + threadIdx.x;
    if (i < NN) {
        int r = g_rowptr[i] + g_bsum[i >> 9];
        g_rowptr[i] = r;
        g_cursor[i] = r;
        float deg = (float)(g_cd[i] & ((1ull << 40) - 1)) * (1.0f / 1048576.0f);
        g_dinv[i] = rsqrtf(deg + 1.0f);
    }
    if (i == 0) g_rowptr[NN] = E;
}

// ---- 5) scatter: one int2 {src, coef} per edge ----
__global__ void k_scatter(const int* __restrict__ ei, const float* __restrict__ ew, int E) {
    int i = blockIdx.x * blockDim.x + threadIdx.x;
    if (i >= E) return;
    int s = ei[i];
    int d = ei[E + i];
    float coef = __ldg(&g_dinv[s]) * ew[i] * __ldg(&g_dinv[d]);
    int pos = atomicAdd(&g_cursor[d], 1);
    g_csr[pos] = make_int2(s, __float_as_int(coef));
}

// ---- 6) xw1 = x @ W1 (128 -> 16): register-blocked, 1 node/thread ----
__global__ void __launch_bounds__(128) k_xw(const float* __restrict__ x,
                                            const float* __restrict__ W1) {
    __shared__ float xsT[64 * 129];   // k-major, padded
    __shared__ float Ws[2048];        // 128 x 16
    int tid = threadIdx.x;
    int base = blockIdx.x * 128;
    for (int i = tid; i < 2048; i += 128) Ws[i] = W1[i];

    float acc[16];
#pragma unroll
    for (int c = 0; c < 16; c++) acc[c] = 0.f;
    int node = base + tid;

    for (int half = 0; half < 2; half++) {
        __syncthreads();
        // stage 128 nodes x 64 k, transposed to k-major (coalesced global reads)
        for (int i = tid; i < 128 * 64; i += 128) {
            int n = i >> 6, k = i & 63;
            int gn = base + n;
            float v = (gn < NN) ? x[(long long)gn * 128 + half * 64 + k] : 0.f;
            xsT[k * 129 + n] = v;
        }
        __syncthreads();
#pragma unroll 4
        for (int k = 0; k < 64; k++) {
            float xv = xsT[k * 129 + tid];
            const float4* wr = (const float4*)(Ws + (half * 64 + k) * 16);
            float4 w0 = wr[0], w1 = wr[1], w2 = wr[2], w3 = wr[3];
            acc[0]  = fmaf(xv, w0.x, acc[0]);  acc[1]  = fmaf(xv, w0.y, acc[1]);
            acc[2]  = fmaf(xv, w0.z, acc[2]);  acc[3]  = fmaf(xv, w0.w, acc[3]);
            acc[4]  = fmaf(xv, w1.x, acc[4]);  acc[5]  = fmaf(xv, w1.y, acc[5]);
            acc[6]  = fmaf(xv, w1.z, acc[6]);  acc[7]  = fmaf(xv, w1.w, acc[7]);
            acc[8]  = fmaf(xv, w2.x, acc[8]);  acc[9]  = fmaf(xv, w2.y, acc[9]);
            acc[10] = fmaf(xv, w2.z, acc[10]); acc[11] = fmaf(xv, w2.w, acc[11]);
            acc[12] = fmaf(xv, w3.x, acc[12]); acc[13] = fmaf(xv, w3.y, acc[13]);
            acc[14] = fmaf(xv, w3.z, acc[14]); acc[15] = fmaf(xv, w3.w, acc[15]);
        }
    }
    if (node < NN) {
        float4* o = (float4*)(g_xw1 + (long long)node * 16);
        o[0] = make_float4(acc[0],  acc[1],  acc[2],  acc[3]);
        o[1] = make_float4(acc[4],  acc[5],  acc[6],  acc[7]);
        o[2] = make_float4(acc[8],  acc[9],  acc[10], acc[11]);
        o[3] = make_float4(acc[12], acc[13], acc[14], acc[15]);
    }
}

// ---- 7) layer-1 aggregation + bias + relu; 8 threads/node, float2 channels ----
__global__ void k_agg1(const float* __restrict__ b1) {
    int t = blockIdx.x * blockDim.x + threadIdx.x;
    int node = t >> 3;
    int c2 = t & 7;
    if (node >= NN) return;
    const float2* xw = (const float2*)g_xw1;
    int j0 = g_rowptr[node], j1 = g_rowptr[node + 1];
    float dv = g_dinv[node];
    float2 self = xw[node * 8 + c2];
    float acc0 = self.x * dv * dv, acc1 = self.y * dv * dv;
#pragma unroll 4
    for (int j = j0; j < j1; j++) {
        int2 e = g_csr[j];
        float w = __int_as_float(e.y);
        float2 v = xw[e.x * 8 + c2];
        acc0 = fmaf(v.x, w, acc0);
        acc1 = fmaf(v.y, w, acc1);
    }
    float2 o;
    o.x = fmaxf(acc0 + b1[2 * c2], 0.f);
    o.y = fmaxf(acc1 + b1[2 * c2 + 1], 0.f);
    ((float2*)g_h)[node * 8 + c2] = o;
}

// ---- 8) layer-2 aggregation over h (16ch); az into g_xw1 (dead after agg1) ----
__global__ void k_agg2() {
    int t = blockIdx.x * blockDim.x + threadIdx.x;
    int node = t >> 3;
    int c2 = t & 7;
    if (node >= NN) return;
    const float2* hh = (const float2*)g_h;
    int j0 = g_rowptr[node], j1 = g_rowptr[node + 1];
    float dv = g_dinv[node];
    float2 self = hh[node * 8 + c2];
    float acc0 = self.x * dv * dv, acc1 = self.y * dv * dv;
#pragma unroll 4
    for (int j = j0; j < j1; j++) {
        int2 e = g_csr[j];
        float w = __int_as_float(e.y);
        float2 v = hh[e.x * 8 + c2];
        acc0 = fmaf(v.x, w, acc0);
        acc1 = fmaf(v.y, w, acc1);
    }
    ((float2*)g_xw1)[node * 8 + c2] = make_float2(acc0, acc1);
}

// ---- 9) out = az @ W2 + b2 (16 -> 32), 8 nodes per 256-thread block ----
__global__ void k_out(const float* __restrict__ W2, const float* __restrict__ b2,
                      float* __restrict__ out) {
    __shared__ float Ws[16 * 32];
    __shared__ float hs[8 * 16];
    int tid = threadIdx.x;
    int base = blockIdx.x * 8;
    for (int i = tid; i < 512; i += 256) Ws[i] = W2[i];
    if (tid < 128) hs[tid] = g_xw1[base * 16 + tid];   // az
    __syncthreads();
    int r = tid >> 5, c = tid & 31;
    float acc = b2[c];
#pragma unroll
    for (int k = 0; k < 16; k++) acc = fmaf(hs[r * 16 + k], Ws[k * 32 + c], acc);
    out[(base + r) * 32 + c] = acc;
}

extern "C" void kernel_launch(void* const* d_in, const int* in_sizes, int n_in,
                              void* d_out, int out_size) {
    const float* x  = (const float*)d_in[0];
    const int*   ei = (const int*)d_in[1];
    const float* ew = (const float*)d_in[2];
    const float* W1 = (const float*)d_in[3];
    const float* b1 = (const float*)d_in[4];
    const float* W2 = (const float*)d_in[5];
    const float* b2 = (const float*)d_in[6];
    float* out = (float*)d_out;
    int E = in_sizes[2];           // 3200000

    int nblkN = (NN + 255) / 256;
    int nblkE = (E + 255) / 256;
    int nblkA = (NN * 8 + 255) / 256;

    k_zero<<<nblkN, 256>>>();
    k_pre<<<nblkE, 256>>>(ei, ew, E);
    k_scan1<<<NB_SCAN, 512>>>();
    k_scan2<<<1, 256>>>();
    k_scan3<<<nblkN, 256>>>(E);
    k_scatter<<<nblkE, 256>>>(ei, ew, E);
    k_xw<<<(NN + 127) / 128, 128>>>(x, W1);
    k_agg1<<<nblkA, 256>>>(b1);
    k_agg2<<<nblkA, 256>>>();
    k_out<<<NN / 8, 256>>>(W2, b2, out);
}